// round 1
// baseline (speedup 1.0000x reference)
#include <cuda_runtime.h>
#include <cuda_bf16.h>
#include <cstdint>

#define NUM_USERS 100000
#define NUM_ITEMS 100000
#define N_TOTAL   200000
#define DIM       64
#define E_EDGES   3200000

// ---------------- scratch (device globals: no allocation allowed) ----------
__device__ float g_x   [N_TOTAL * DIM];   // layer input x
__device__ float g_agg [N_TOTAL * DIM];   // accumulator (init = x, then += scatter)
__device__ float g_h   [N_TOTAL * DIM];   // layer-1 output
__device__ int4  g_edesc[E_EDGES];        // packed {src, dst, w_bits, 0}
__device__ int   g_is64;

// ---------------- detect index dtype (int64 vs int32) ----------------------
__global__ void detect_kernel(const long long* __restrict__ ei) {
    if (blockIdx.x == 0 && threadIdx.x == 0) {
        int ok = 1;
        #pragma unroll 1
        for (int i = 0; i < 64; i++) {
            long long v = ei[i];
            if (v < 0 || v >= (long long)N_TOTAL) { ok = 0; break; }
        }
        g_is64 = ok;
    }
}

// ---------------- normalize indices into packed descriptors ----------------
__global__ void normalize_kernel(const void* __restrict__ ei,
                                 const float* __restrict__ w) {
    int i = blockIdx.x * blockDim.x + threadIdx.x;
    if (i >= E_EDGES) return;
    int s, t;
    if (g_is64) {
        const long long* p = (const long long*)ei;
        s = (int)p[i];
        t = (int)p[E_EDGES + i];
    } else {
        const int* p = (const int*)ei;
        s = p[i];
        t = p[E_EDGES + i];
    }
    g_edesc[i] = make_int4(s, t, __float_as_int(w[i]), 0);
}

// ---------------- build x = concat(user, item); agg = x --------------------
__global__ void init_x_kernel(const float4* __restrict__ ue,
                              const float4* __restrict__ ie) {
    int i = blockIdx.x * blockDim.x + threadIdx.x;
    const int total = N_TOTAL * DIM / 4;          // 3.2M float4
    const int usplit = NUM_USERS * DIM / 4;       // 1.6M
    if (i >= total) return;
    float4 v = (i < usplit) ? ue[i] : ie[i - usplit];
    reinterpret_cast<float4*>(g_x)[i]   = v;
    reinterpret_cast<float4*>(g_agg)[i] = v;
}

// ---------------- scatter: agg[dst] += w * x[src] --------------------------
// 4 threads per edge, each thread handles 4 float4 (64B) of the 256B row.
__global__ void __launch_bounds__(256) scatter_kernel(
        const float* __restrict__ x, float* __restrict__ agg) {
    unsigned gt = blockIdx.x * blockDim.x + threadIdx.x;
    unsigned e  = gt >> 2;
    if (e >= E_EDGES) return;
    int sub = gt & 3;

    int4 d = g_edesc[e];                       // broadcast within 4-thread group
    int s = d.x, t = d.y;
    float w = __int_as_float(d.z);

    const float4* xs = reinterpret_cast<const float4*>(x + (size_t)s * DIM) + sub * 4;
    float4*       ap = reinterpret_cast<float4*>(agg + (size_t)t * DIM) + sub * 4;

    float4 v0 = xs[0], v1 = xs[1], v2 = xs[2], v3 = xs[3];
    v0.x *= w; v0.y *= w; v0.z *= w; v0.w *= w;
    v1.x *= w; v1.y *= w; v1.z *= w; v1.w *= w;
    v2.x *= w; v2.y *= w; v2.z *= w; v2.w *= w;
    v3.x *= w; v3.y *= w; v3.z *= w; v3.w *= w;

    asm volatile("red.global.add.v4.f32 [%0], {%1,%2,%3,%4};"
                 :: "l"(ap + 0), "f"(v0.x), "f"(v0.y), "f"(v0.z), "f"(v0.w) : "memory");
    asm volatile("red.global.add.v4.f32 [%0], {%1,%2,%3,%4};"
                 :: "l"(ap + 1), "f"(v1.x), "f"(v1.y), "f"(v1.z), "f"(v1.w) : "memory");
    asm volatile("red.global.add.v4.f32 [%0], {%1,%2,%3,%4};"
                 :: "l"(ap + 2), "f"(v2.x), "f"(v2.y), "f"(v2.z), "f"(v2.w) : "memory");
    asm volatile("red.global.add.v4.f32 [%0], {%1,%2,%3,%4};"
                 :: "l"(ap + 3), "f"(v3.x), "f"(v3.y), "f"(v3.z), "f"(v3.w) : "memory");
}

// ---------------- linear: out = 0.5 * in @ W + b ---------------------------
// One warp per row. W staged in smem [64x64], input row broadcast-loaded.
// Also optionally mirrors the result into out2 (next layer's accumulator init).
__global__ void __launch_bounds__(256) linear_kernel(
        const float* __restrict__ in, const float* __restrict__ W,
        const float* __restrict__ b, float* __restrict__ out,
        float* __restrict__ out2) {
    __shared__ float Ws[DIM * DIM];
    __shared__ float bs[DIM];
    for (int i = threadIdx.x; i < DIM * DIM; i += blockDim.x) Ws[i] = W[i];
    if (threadIdx.x < DIM) bs[threadIdx.x] = b[threadIdx.x];
    __syncthreads();

    int lane  = threadIdx.x & 31;
    int warp  = threadIdx.x >> 5;
    int nwpb  = blockDim.x >> 5;
    int stride = gridDim.x * nwpb;

    for (int row = blockIdx.x * nwpb + warp; row < N_TOTAL; row += stride) {
        const float4* rp = reinterpret_cast<const float4*>(in + (size_t)row * DIM);
        float acc0 = 0.f, acc1 = 0.f;
        #pragma unroll
        for (int kk = 0; kk < 16; kk++) {
            float4 v = rp[kk];              // same addr all lanes -> broadcast
            int k = kk * 4;
            acc0 += v.x * Ws[(k + 0) * DIM + lane]
                  + v.y * Ws[(k + 1) * DIM + lane]
                  + v.z * Ws[(k + 2) * DIM + lane]
                  + v.w * Ws[(k + 3) * DIM + lane];
            acc1 += v.x * Ws[(k + 0) * DIM + 32 + lane]
                  + v.y * Ws[(k + 1) * DIM + 32 + lane]
                  + v.z * Ws[(k + 2) * DIM + 32 + lane]
                  + v.w * Ws[(k + 3) * DIM + 32 + lane];
        }
        float r0 = 0.5f * acc0 + bs[lane];
        float r1 = 0.5f * acc1 + bs[32 + lane];
        size_t o = (size_t)row * DIM;
        out[o + lane]      = r0;
        out[o + 32 + lane] = r1;
        if (out2) {
            out2[o + lane]      = r0;
            out2[o + 32 + lane] = r1;
        }
    }
}

// ---------------- launch ----------------------------------------------------
extern "C" void kernel_launch(void* const* d_in, const int* in_sizes, int n_in,
                              void* d_out, int out_size) {
    const void*  ei = d_in[0];
    const float* ew = (const float*)d_in[1];
    const float* ue = (const float*)d_in[2];
    const float* ie = (const float*)d_in[3];
    const float* W1 = (const float*)d_in[4];
    const float* b1 = (const float*)d_in[5];
    const float* W2 = (const float*)d_in[6];
    const float* b2 = (const float*)d_in[7];
    float* out = (float*)d_out;

    float *px, *pagg, *ph;
    cudaGetSymbolAddress((void**)&px,   g_x);
    cudaGetSymbolAddress((void**)&pagg, g_agg);
    cudaGetSymbolAddress((void**)&ph,   g_h);

    detect_kernel<<<1, 32>>>((const long long*)ei);

    {
        int threads = 256, blocks = (E_EDGES + threads - 1) / threads;
        normalize_kernel<<<blocks, threads>>>(ei, ew);
    }
    {
        int total = N_TOTAL * DIM / 4;
        int threads = 256, blocks = (total + threads - 1) / threads;
        init_x_kernel<<<blocks, threads>>>((const float4*)ue, (const float4*)ie);
    }

    const int sc_threads = 256;
    const int sc_blocks  = (E_EDGES * 4 + sc_threads - 1) / sc_threads;
    const int ln_blocks  = 2048;

    // Layer 1
    scatter_kernel<<<sc_blocks, sc_threads>>>(px, pagg);
    linear_kernel<<<ln_blocks, 256>>>(pagg, W1, b1, ph, pagg /* init next acc */);

    // Layer 2
    scatter_kernel<<<sc_blocks, sc_threads>>>(ph, pagg);
    linear_kernel<<<ln_blocks, 256>>>(pagg, W2, b2, out, nullptr);
}

// round 3
// speedup vs baseline: 1.3321x; 1.3321x over previous
#include <cuda_runtime.h>
#include <cuda_bf16.h>
#include <cstdint>

#define NUM_USERS 100000
#define NUM_ITEMS 100000
#define N_TOTAL   200000
#define DIM       64
#define E_EDGES   3200000
#define SCAN_CHUNK 1024
#define SCAN_NBLK  ((N_TOTAL + SCAN_CHUNK - 1) / SCAN_CHUNK)   // 196

// ---------------- scratch (device globals: no allocation allowed) ----------
__device__ float g_x   [N_TOTAL * DIM];   // layer-0 input x
__device__ float g_agg [N_TOTAL * DIM];   // aggregated (x + scatter) rows
__device__ float g_h   [N_TOTAL * DIM];   // layer-1 output
__device__ int4  g_edesc[E_EDGES];        // {src, dst, w_bits, 0}
__device__ int2  g_esrt [E_EDGES];        // dst-sorted: {src, w_bits}
__device__ int   g_cnt [N_TOTAL];
__device__ int   g_off [N_TOTAL];
__device__ int   g_cur [N_TOTAL];
__device__ int   g_bsum[SCAN_NBLK];
__device__ int   g_is64;

// ---------------- detect index dtype (int64 vs int32) ----------------------
__global__ void detect_kernel(const long long* __restrict__ ei) {
    if (threadIdx.x == 0) {
        int ok = 1;
        #pragma unroll 1
        for (int i = 0; i < 64; i++) {
            long long v = ei[i];
            if (v < 0 || v >= (long long)N_TOTAL) { ok = 0; break; }
        }
        g_is64 = ok;
    }
}

// ---------------- normalize indices + histogram dst ------------------------
__global__ void normalize_count_kernel(const void* __restrict__ ei,
                                       const float* __restrict__ w) {
    int i = blockIdx.x * blockDim.x + threadIdx.x;
    if (i >= E_EDGES) return;
    int s, t;
    if (g_is64) {
        const long long* p = (const long long*)ei;
        s = (int)p[i];
        t = (int)p[E_EDGES + i];
    } else {
        const int* p = (const int*)ei;
        s = p[i];
        t = p[E_EDGES + i];
    }
    g_edesc[i] = make_int4(s, t, __float_as_int(w[i]), 0);
    atomicAdd(&g_cnt[t], 1);
}

// ---------------- 3-phase exclusive scan of g_cnt -> g_off -----------------
__global__ void __launch_bounds__(SCAN_CHUNK) scan1_kernel() {
    __shared__ int sm[SCAN_CHUNK];
    int t = threadIdx.x;
    int i = blockIdx.x * SCAN_CHUNK + t;
    int v = (i < N_TOTAL) ? g_cnt[i] : 0;
    sm[t] = v;
    __syncthreads();
    for (int d = 1; d < SCAN_CHUNK; d <<= 1) {
        int a = (t >= d) ? sm[t - d] : 0;
        __syncthreads();
        sm[t] += a;
        __syncthreads();
    }
    if (i < N_TOTAL) g_off[i] = sm[t] - v;       // exclusive
    if (t == SCAN_CHUNK - 1) g_bsum[blockIdx.x] = sm[t];
}

__global__ void scan2_kernel() {
    __shared__ int sm[256];
    int t = threadIdx.x;
    int v = (t < SCAN_NBLK) ? g_bsum[t] : 0;
    sm[t] = v;
    __syncthreads();
    for (int d = 1; d < 256; d <<= 1) {
        int a = (t >= d) ? sm[t - d] : 0;
        __syncthreads();
        sm[t] += a;
        __syncthreads();
    }
    if (t < SCAN_NBLK) g_bsum[t] = sm[t] - v;    // exclusive
}

__global__ void scan3_kernel() {
    int i = blockIdx.x * blockDim.x + threadIdx.x;
    if (i >= N_TOTAL) return;
    int o = g_off[i] + g_bsum[i >> 10];
    g_off[i] = o;
    g_cur[i] = o;
}

// ---------------- placement: dst-sorted edge list --------------------------
__global__ void place_kernel() {
    int i = blockIdx.x * blockDim.x + threadIdx.x;
    if (i >= E_EDGES) return;
    int4 d = g_edesc[i];
    int pos = atomicAdd(&g_cur[d.y], 1);
    g_esrt[pos] = make_int2(d.x, d.z);
}

// ---------------- build x = concat(user, item) -----------------------------
__global__ void init_x_kernel(const float4* __restrict__ ue,
                              const float4* __restrict__ ie) {
    int i = blockIdx.x * blockDim.x + threadIdx.x;
    const int total = N_TOTAL * DIM / 4;
    const int usplit = NUM_USERS * DIM / 4;
    if (i >= total) return;
    reinterpret_cast<float4*>(g_x)[i] = (i < usplit) ? ue[i] : ie[i - usplit];
}

// ---------------- segmented aggregation: out[n] = x[n] + sum w*x[src] ------
// One warp per dst node; float2 per lane covers the 64-wide row.
__global__ void __launch_bounds__(256) aggregate_kernel(
        const float* __restrict__ x, float* __restrict__ out) {
    int warp = (blockIdx.x * blockDim.x + threadIdx.x) >> 5;
    int lane = threadIdx.x & 31;
    if (warp >= N_TOTAL) return;

    int start = g_off[warp];
    int cnt   = g_cnt[warp];
    const float2* xp = reinterpret_cast<const float2*>(x);

    float2 acc = xp[(size_t)warp * 32 + lane];   // residual term

    int e = start, end = start + cnt;
    for (; e + 1 < end; e += 2) {
        int2 d0 = g_esrt[e];
        int2 d1 = g_esrt[e + 1];
        float2 v0 = xp[(size_t)d0.x * 32 + lane];
        float2 v1 = xp[(size_t)d1.x * 32 + lane];
        float w0 = __int_as_float(d0.y);
        float w1 = __int_as_float(d1.y);
        acc.x += w0 * v0.x + w1 * v1.x;
        acc.y += w0 * v0.y + w1 * v1.y;
    }
    if (e < end) {
        int2 d0 = g_esrt[e];
        float2 v0 = xp[(size_t)d0.x * 32 + lane];
        float w0 = __int_as_float(d0.y);
        acc.x += w0 * v0.x;
        acc.y += w0 * v0.y;
    }
    reinterpret_cast<float2*>(out)[(size_t)warp * 32 + lane] = acc;
}

// ---------------- linear: out = 0.5 * in @ W + b ---------------------------
__global__ void __launch_bounds__(256) linear_kernel(
        const float* __restrict__ in, const float* __restrict__ W,
        const float* __restrict__ b, float* __restrict__ out) {
    __shared__ float Ws[DIM * DIM];
    __shared__ float bs[DIM];
    for (int i = threadIdx.x; i < DIM * DIM; i += blockDim.x) Ws[i] = W[i];
    if (threadIdx.x < DIM) bs[threadIdx.x] = b[threadIdx.x];
    __syncthreads();

    int lane  = threadIdx.x & 31;
    int warp  = threadIdx.x >> 5;
    int nwpb  = blockDim.x >> 5;
    int stride = gridDim.x * nwpb;

    for (int row = blockIdx.x * nwpb + warp; row < N_TOTAL; row += stride) {
        const float4* rp = reinterpret_cast<const float4*>(in + (size_t)row * DIM);
        float acc0 = 0.f, acc1 = 0.f;
        #pragma unroll
        for (int kk = 0; kk < 16; kk++) {
            float4 v = rp[kk];              // broadcast within warp
            int k = kk * 4;
            acc0 += v.x * Ws[(k + 0) * DIM + lane]
                  + v.y * Ws[(k + 1) * DIM + lane]
                  + v.z * Ws[(k + 2) * DIM + lane]
                  + v.w * Ws[(k + 3) * DIM + lane];
            acc1 += v.x * Ws[(k + 0) * DIM + 32 + lane]
                  + v.y * Ws[(k + 1) * DIM + 32 + lane]
                  + v.z * Ws[(k + 2) * DIM + 32 + lane]
                  + v.w * Ws[(k + 3) * DIM + 32 + lane];
        }
        size_t o = (size_t)row * DIM;
        out[o + lane]      = 0.5f * acc0 + bs[lane];
        out[o + 32 + lane] = 0.5f * acc1 + bs[32 + lane];
    }
}

// ---------------- launch ----------------------------------------------------
extern "C" void kernel_launch(void* const* d_in, const int* in_sizes, int n_in,
                              void* d_out, int out_size) {
    const void*  ei = d_in[0];
    const float* ew = (const float*)d_in[1];
    const float* ue = (const float*)d_in[2];
    const float* ie = (const float*)d_in[3];
    const float* W1 = (const float*)d_in[4];
    const float* b1 = (const float*)d_in[5];
    const float* W2 = (const float*)d_in[6];
    const float* b2 = (const float*)d_in[7];
    float* out = (float*)d_out;

    float *px, *pagg, *ph;
    int   *pcnt;
    cudaGetSymbolAddress((void**)&px,   g_x);
    cudaGetSymbolAddress((void**)&pagg, g_agg);
    cudaGetSymbolAddress((void**)&ph,   g_h);
    cudaGetSymbolAddress((void**)&pcnt, g_cnt);

    cudaMemsetAsync(pcnt, 0, N_TOTAL * sizeof(int));

    detect_kernel<<<1, 32>>>((const long long*)ei);

    normalize_count_kernel<<<(E_EDGES + 255) / 256, 256>>>(ei, ew);

    scan1_kernel<<<SCAN_NBLK, SCAN_CHUNK>>>();
    scan2_kernel<<<1, 256>>>();
    scan3_kernel<<<(N_TOTAL + 255) / 256, 256>>>();

    place_kernel<<<(E_EDGES + 255) / 256, 256>>>();

    init_x_kernel<<<(N_TOTAL * DIM / 4 + 255) / 256, 256>>>(
        (const float4*)ue, (const float4*)ie);

    const int agg_blocks = (N_TOTAL * 32 + 255) / 256;   // 1 warp per node
    const int ln_blocks  = 2048;

    // Layer 1
    aggregate_kernel<<<agg_blocks, 256>>>(px, pagg);
    linear_kernel<<<ln_blocks, 256>>>(pagg, W1, b1, ph);

    // Layer 2
    aggregate_kernel<<<agg_blocks, 256>>>(ph, pagg);
    linear_kernel<<<ln_blocks, 256>>>(pagg, W2, b2, out);
}